// round 15
// baseline (speedup 1.0000x reference)
#include <cuda_runtime.h>
#include <cuda_bf16.h>
#include <cuda_fp16.h>
#include <stdint.h>

#define B_  2
#define S_  4096
#define D_  768
#define H_  12
#define HD_ 64
#define MROWS 8192
#define NELEM (B_*H_*S_*HD_)

// weights single fp16 (activations converted in-GEMM)
__device__ __half g_wqh[D_*D_], g_wkh[D_*D_], g_wvh[D_*D_], g_woh[D_*D_];
// projected Q/K: [b][h][s][hd] fp16 (Q pre-scaled by 0.125*log2e); V transposed [b][h][hd][s] fp16
__device__ __half g_qh[NELEM], g_kh[NELEM], g_vth[NELEM];
// attention output fp16 [b][s][d]
__device__ __half g_ah[MROWS*D_];

// ---------------------------------------------------------------------------
__device__ __forceinline__ uint32_t pack_h2(float x0, float x1) {
    uint32_t r;
    asm("cvt.rn.f16x2.f32 %0, %1, %2;" : "=r"(r) : "f"(x1), "f"(x0));
    return r;
}
__device__ __forceinline__ void mma16816h(float (&c)[4], const uint32_t (&a)[4],
                                          uint32_t b0, uint32_t b1) {
    asm volatile(
        "mma.sync.aligned.m16n8k16.row.col.f32.f16.f16.f32 "
        "{%0,%1,%2,%3}, {%4,%5,%6,%7}, {%8,%9}, {%0,%1,%2,%3};\n"
        : "+f"(c[0]), "+f"(c[1]), "+f"(c[2]), "+f"(c[3])
        : "r"(a[0]), "r"(a[1]), "r"(a[2]), "r"(a[3]), "r"(b0), "r"(b1));
}
__device__ __forceinline__ void ldsm4(uint32_t (&r)[4], uint32_t addr) {
    asm volatile("ldmatrix.sync.aligned.m8n8.x4.shared.b16 {%0,%1,%2,%3}, [%4];"
        : "=r"(r[0]), "=r"(r[1]), "=r"(r[2]), "=r"(r[3]) : "r"(addr));
}
__device__ __forceinline__ uint32_t smem_u32(const void* p) {
    uint32_t a;
    asm("{ .reg .u64 t; cvta.to.shared.u64 t, %1; cvt.u32.u64 %0, t; }" : "=r"(a) : "l"(p));
    return a;
}
__device__ __forceinline__ void cp16(uint32_t d, const void* s) {
    asm volatile("cp.async.ca.shared.global [%0], [%1], 16;" :: "r"(d), "l"(s));
}
__device__ __forceinline__ void cp_commit() { asm volatile("cp.async.commit_group;"); }
template<int N> __device__ __forceinline__ void cp_wait() {
    asm volatile("cp.async.wait_group %0;" :: "n"(N));
}

// ---------------------------------------------------------------------------
// prep: weights -> single fp16
// ---------------------------------------------------------------------------
__global__ void split_wts(const float* __restrict__ wq, const float* __restrict__ wk,
                          const float* __restrict__ wv, const float* __restrict__ wo) {
    int z = blockIdx.y;
    const float* src = (z == 0) ? wq : (z == 1) ? wk : (z == 2) ? wv : wo;
    __half* h = (z == 0) ? g_wqh : (z == 1) ? g_wkh : (z == 2) ? g_wvh : g_woh;
    int n4 = D_ * D_ / 4;
    for (int i = blockIdx.x * blockDim.x + threadIdx.x; i < n4;
         i += gridDim.x * blockDim.x) {
        float4 v4 = ((const float4*)src)[i];
        uint2 hw;
        hw.x = pack_h2(v4.x, v4.y);
        hw.y = pack_h2(v4.z, v4.w);
        ((uint2*)h)[i] = hw;
    }
}

// ---------------------------------------------------------------------------
// GEMM: C = X @ W^T + bias. W fp16 via cp.async (3-stage ring, one barrier
// per stage). X fp32 (fused cvt path) or fp16 (cp.async). 128x128x32 tiles,
// 256 thr = 8 warps (4m x 2n). LDSM B-fragments double-buffered.
// ---------------------------------------------------------------------------
#define GSTG 5120
#define GEMM_SMEM (3 * GSTG * 4)

template<bool XF32>
__device__ __forceinline__ void gemm_core(
    const float* __restrict__ Xf, const __half* __restrict__ Xh,
    const __half* __restrict__ Wh,
    const float* __restrict__ bias, float osc, int emode,
    __half* __restrict__ outh, float* __restrict__ outf)
{
    extern __shared__ uint32_t sm[];
    const uint32_t smb = smem_u32(sm);

    const int tid  = threadIdx.x;
    const int lane = tid & 31;
    const int warp = tid >> 5;
    const int wm = warp >> 1, wn = warp & 1;
    const int g = lane >> 2, t = lane & 3;
    const int m0 = blockIdx.y * 128;
    const int n0 = blockIdx.x * 128;

    const uint32_t la = (uint32_t)(((wm * 32 + (lane & 7) + ((lane >> 3) & 1) * 8) * 20) * 4
                                   + ((lane >> 4) & 1) * 16);
    const uint32_t lb = (uint32_t)(((wn * 64 + ((lane >> 4) & 1) * 8 + (lane & 7)) * 20) * 4
                                   + ((lane >> 3) & 1) * 16);

    auto issueW = [&](int kt, int s) {
        int k0 = kt * 32;
        #pragma unroll
        for (int p = 0; p < 2; p++) {
            int idx = p * 256 + tid;
            int r = idx >> 2, c8 = (idx & 3) * 8;
            uint32_t dst = smb + (uint32_t)((s * GSTG + 2560 + r * 20 + (c8 >> 1)) * 4);
            cp16(dst, Wh + (size_t)(n0 + r) * D_ + k0 + c8);
        }
        cp_commit();
    };
    auto issueXW = [&](int kt, int s) {
        int k0 = kt * 32;
        #pragma unroll
        for (int p = 0; p < 2; p++) {
            int idx = p * 256 + tid;
            int r = idx >> 2, c8 = (idx & 3) * 8;
            uint32_t dst = smb + (uint32_t)((s * GSTG + r * 20 + (c8 >> 1)) * 4);
            cp16(dst,            Xh + (size_t)(m0 + r) * D_ + k0 + c8);
            cp16(dst + 2560 * 4, Wh + (size_t)(n0 + r) * D_ + k0 + c8);
        }
        cp_commit();
    };

    float4 pa[4];
    auto loadX = [&](int kt) {
        int k0 = kt * 32;
        #pragma unroll
        for (int p = 0; p < 2; p++) {
            int idx = p * 256 + tid;
            int r = idx >> 2, c8 = (idx & 3) * 8;
            const float* src = Xf + (size_t)(m0 + r) * D_ + k0 + c8;
            pa[p * 2]     = *(const float4*)src;
            pa[p * 2 + 1] = *(const float4*)(src + 4);
        }
    };
    auto stsX = [&](int s) {
        #pragma unroll
        for (int p = 0; p < 2; p++) {
            int idx = p * 256 + tid;
            int r = idx >> 2, c8 = (idx & 3) * 8;
            uint32_t dst = smb + (uint32_t)((s * GSTG + r * 20 + (c8 >> 1)) * 4);
            uint32_t w0 = pack_h2(pa[p * 2].x,     pa[p * 2].y);
            uint32_t w1 = pack_h2(pa[p * 2].z,     pa[p * 2].w);
            uint32_t w2 = pack_h2(pa[p * 2 + 1].x, pa[p * 2 + 1].y);
            uint32_t w3 = pack_h2(pa[p * 2 + 1].z, pa[p * 2 + 1].w);
            asm volatile("st.shared.v4.b32 [%0], {%1,%2,%3,%4};"
                :: "r"(dst), "r"(w0), "r"(w1), "r"(w2), "r"(w3));
        }
    };

    float c[2][8][4];
    #pragma unroll
    for (int fi = 0; fi < 2; fi++)
        #pragma unroll
        for (int fj = 0; fj < 8; fj++)
            #pragma unroll
            for (int e = 0; e < 4; e++) c[fi][fj][e] = 0.0f;

    if (XF32) {
        loadX(0);
        stsX(0);
        loadX(1);
        issueW(0, 0);
        issueW(1, 1);
    } else {
        issueXW(0, 0);
        issueXW(1, 1);
    }

    int sidx = 0;
    for (int kt = 0; kt < 24; kt++) {
        if (kt < 23) cp_wait<1>();
        else         cp_wait<0>();
        __syncthreads();

        int sn = sidx + 2; if (sn >= 3) sn -= 3;
        if (XF32) {
            if (kt + 1 < 24) {
                int s1 = sidx + 1; if (s1 >= 3) s1 -= 3;
                stsX(s1);
            }
            if (kt + 2 < 24) {
                loadX(kt + 2);
                issueW(kt + 2, sn);
            }
        } else {
            if (kt + 2 < 24) issueXW(kt + 2, sn);
        }

        uint32_t Ab = smb + (uint32_t)(sidx * GSTG * 4);
        uint32_t Bb = Ab + 2560 * 4;

        #pragma unroll
        for (int ks = 0; ks < 2; ks++) {
            uint32_t ah[2][4];
            #pragma unroll
            for (int fi = 0; fi < 2; fi++)
                ldsm4(ah[fi], Ab + la + (uint32_t)(fi * 16 * 20 * 4 + ks * 32));
            uint32_t bf[2][4];
            ldsm4(bf[0], Bb + lb + (uint32_t)(ks * 32));
            #pragma unroll
            for (int p = 0; p < 4; p++) {
                int cur = p & 1;
                if (p < 3)
                    ldsm4(bf[cur ^ 1], Bb + lb + (uint32_t)((p + 1) * 16 * 20 * 4 + ks * 32));
                #pragma unroll
                for (int fi = 0; fi < 2; fi++) {
                    mma16816h(c[fi][2 * p],     ah[fi], bf[cur][0], bf[cur][1]);
                    mma16816h(c[fi][2 * p + 1], ah[fi], bf[cur][2], bf[cur][3]);
                }
            }
        }
        sidx = (sidx + 1 == 3) ? 0 : sidx + 1;
    }

    #pragma unroll
    for (int fi = 0; fi < 2; fi++) {
        #pragma unroll
        for (int rr = 0; rr < 2; rr++) {
            int m = m0 + wm * 32 + fi * 16 + g + rr * 8;
            #pragma unroll
            for (int fj = 0; fj < 8; fj++) {
                int n = n0 + wn * 64 + fj * 8 + 2 * t;
                float v0 = c[fi][fj][rr * 2 + 0] + bias[n];
                float v1 = c[fi][fj][rr * 2 + 1] + bias[n + 1];
                if (emode <= 1) {
                    v0 *= osc; v1 *= osc;
                    int bb = m >> 12, ss = m & 4095;
                    int hh = n >> 6,  hd = n & 63;
                    size_t off = (((size_t)bb * H_ + hh) * S_ + ss) * HD_ + hd;
                    *(uint32_t*)&outh[off] = pack_h2(v0, v1);
                } else if (emode == 2) {
                    int bb = m >> 12, ss = m & 4095;
                    int hh = n >> 6,  hd = n & 63;
                    size_t base = (((size_t)bb * H_ + hh) * HD_ + hd) * S_ + ss;
                    outh[base]      = __float2half_rn(v0);
                    outh[base + S_] = __float2half_rn(v1);
                } else {
                    float2 o2; o2.x = v0; o2.y = v1;
                    *(float2*)&outf[(size_t)m * D_ + n] = o2;
                }
            }
        }
    }
}

__global__ void __launch_bounds__(256, 2) proj_qkv(
    const float* __restrict__ xq, const float* __restrict__ xk, const float* __restrict__ xv,
    const float* __restrict__ bq, const float* __restrict__ bk, const float* __restrict__ bv)
{
    int z = blockIdx.z;
    const float* Xf = (z == 0) ? xq : (z == 1) ? xk : xv;
    const __half* Wh = (z == 0) ? g_wqh : (z == 1) ? g_wkh : g_wvh;
    const float* bias = (z == 0) ? bq : (z == 1) ? bk : bv;
    __half* oh = (z == 0) ? g_qh : (z == 1) ? g_kh : g_vth;
    float osc = (z == 0) ? (0.125f * 1.44269504f) : 1.0f;   // Q: fold 1/8 and log2(e)
    gemm_core<true>(Xf, nullptr, Wh, bias, osc, z, oh, nullptr);
}

__global__ void __launch_bounds__(256, 2) proj_out(
    const float* __restrict__ bo, float* __restrict__ out)
{
    gemm_core<false>(nullptr, g_ah, g_woh, bo, 1.0f, 3, nullptr, out);
}

// ---------------------------------------------------------------------------
// Flash attention, causal, single-fp16 MMA, log2-domain softmax, l via
// constant ones B-fragment. 128 q-rows/CTA (4 warps x 32 rows), 64-key tiles.
// 3-stage cp.async ring, ONE barrier per tile. Warp-uniform rescale skip.
// PV hoisted out of the fi loop (V read ONCE per tile) and LDSM fragments
// double-buffered in both QK and PV. Stage: K 64x36, V 64x36 words.
// ---------------------------------------------------------------------------
#define ASTG 4608   // words per stage
#define ATT_SMEM (3 * ASTG * 4)

__global__ void __launch_bounds__(128, 2) attn_kernel()
{
    extern __shared__ uint32_t sm[];
    const uint32_t smb = smem_u32(sm);

    const int tid  = threadIdx.x;
    const int lane = tid & 31;
    const int wm   = tid >> 5;
    const int g    = lane >> 2;
    const int t    = lane & 3;
    const int qt = gridDim.x - 1 - blockIdx.x;   // heavy CTAs first
    const int bh = blockIdx.y;
    const int bb = bh / H_;
    const int hh = bh % H_;
    const int q0 = qt * 128;
    const int ntiles = 2 * qt + 2;

    const uint32_t lk = (uint32_t)(((((lane >> 4) & 1) * 8 + (lane & 7)) * 36) * 4
                                   + ((lane >> 3) & 1) * 16);
    const uint32_t ones = (lane < 4) ? 0x3C003C00u : 0u;

    auto issue = [&](int jt, int s) {
        int k0 = jt * 64;
        #pragma unroll
        for (int p = 0; p < 4; p++) {
            int idx = p * 128 + tid;
            int row = idx >> 3, c8 = (idx & 7) * 8;
            uint32_t dstK = smb + (uint32_t)((s * ASTG + row * 36 + (c8 >> 1)) * 4);
            cp16(dstK,            g_kh  + ((size_t)bh * S_ + k0 + row) * HD_ + c8);
            cp16(dstK + 2304 * 4, g_vth + ((size_t)bh * HD_ + row) * S_ + k0 + c8);
        }
        cp_commit();
    };

    issue(0, 0);
    issue(1, 1);

    uint32_t qh[2][4][4];
    #pragma unroll
    for (int fi = 0; fi < 2; fi++) {
        const __half* qb = g_qh + ((size_t)bh * S_ + q0 + wm * 32 + fi * 16) * HD_;
        #pragma unroll
        for (int kt = 0; kt < 4; kt++) {
            int kc = kt * 16 + 2 * t;
            qh[fi][kt][0] = *(const uint32_t*)&qb[(size_t)g * HD_ + kc];
            qh[fi][kt][1] = *(const uint32_t*)&qb[(size_t)(g + 8) * HD_ + kc];
            qh[fi][kt][2] = *(const uint32_t*)&qb[(size_t)g * HD_ + kc + 8];
            qh[fi][kt][3] = *(const uint32_t*)&qb[(size_t)(g + 8) * HD_ + kc + 8];
        }
    }

    float o[2][9][4];
    float mrun[2][2];
    #pragma unroll
    for (int fi = 0; fi < 2; fi++) {
        mrun[fi][0] = mrun[fi][1] = -1e30f;
        #pragma unroll
        for (int fj = 0; fj < 9; fj++)
            #pragma unroll
            for (int e = 0; e < 4; e++) o[fi][fj][e] = 0.0f;
    }

    const int wrow = q0 + wm * 32;
    int sidx = 0;

    for (int jt = 0; jt < ntiles; jt++) {
        const int k0 = jt * 64;
        if (jt + 1 < ntiles) cp_wait<1>();
        else                 cp_wait<0>();
        __syncthreads();

        if (jt + 2 < ntiles) {
            int sn = sidx + 2; if (sn >= 3) sn -= 3;
            issue(jt + 2, sn);
        }

        uint32_t Kb = smb + (uint32_t)(sidx * ASTG * 4) + lk;
        uint32_t Vb = Kb + 2304 * 4;

        // S = Q @ K^T (log2 units); K fragments double-buffered
        float s[2][8][4];
        #pragma unroll
        for (int fi = 0; fi < 2; fi++)
            #pragma unroll
            for (int fj = 0; fj < 8; fj++)
                #pragma unroll
                for (int e = 0; e < 4; e++) s[fi][fj][e] = 0.0f;

        {
            uint32_t kf[2][4];
            ldsm4(kf[0], Kb);   // (kt=0, p=0)
            #pragma unroll
            for (int i = 0; i < 16; i++) {
                int cur = i & 1;
                if (i < 15) {
                    int j = i + 1;
                    ldsm4(kf[cur ^ 1],
                          Kb + (uint32_t)((j & 3) * 2304 + (j >> 2) * 32));
                }
                int kt = i >> 2, p = i & 3;
                mma16816h(s[0][2 * p],     qh[0][kt], kf[cur][0], kf[cur][1]);
                mma16816h(s[0][2 * p + 1], qh[0][kt], kf[cur][2], kf[cur][3]);
                mma16816h(s[1][2 * p],     qh[1][kt], kf[cur][0], kf[cur][1]);
                mma16816h(s[1][2 * p + 1], qh[1][kt], kf[cur][2], kf[cur][3]);
            }
        }

        if (k0 + 63 > wrow) {
            #pragma unroll
            for (int fi = 0; fi < 2; fi++) {
                int r0 = wrow + fi * 16 + g;
                int r1 = r0 + 8;
                #pragma unroll
                for (int fj = 0; fj < 8; fj++) {
                    int cn = k0 + fj * 8 + 2 * t;
                    if (cn     > r0) s[fi][fj][0] = -1e30f;
                    if (cn + 1 > r0) s[fi][fj][1] = -1e30f;
                    if (cn     > r1) s[fi][fj][2] = -1e30f;
                    if (cn + 1 > r1) s[fi][fj][3] = -1e30f;
                }
            }
        }

        // softmax + P packing for BOTH halves, then one PV pass
        uint32_t ph2[2][4][4];
        #pragma unroll
        for (int fi = 0; fi < 2; fi++) {
            float mnew2[2], scale2[2];
            #pragma unroll
            for (int r = 0; r < 2; r++) {
                float mx = -1e30f;
                #pragma unroll
                for (int fj = 0; fj < 8; fj++)
                    mx = fmaxf(mx, fmaxf(s[fi][fj][2 * r], s[fi][fj][2 * r + 1]));
                mx = fmaxf(mx, __shfl_xor_sync(0xffffffffu, mx, 1));
                mx = fmaxf(mx, __shfl_xor_sync(0xffffffffu, mx, 2));
                float mnew  = fmaxf(mrun[fi][r], mx);
                scale2[r] = exp2f(mrun[fi][r] - mnew);
                mrun[fi][r] = mnew;
                mnew2[r] = mnew;
            }
            unsigned noscale = __all_sync(0xffffffffu,
                (scale2[0] == 1.0f) && (scale2[1] == 1.0f));
            if (!noscale) {
                #pragma unroll
                for (int r = 0; r < 2; r++)
                    #pragma unroll
                    for (int fj = 0; fj < 9; fj++) {
                        o[fi][fj][2 * r]     *= scale2[r];
                        o[fi][fj][2 * r + 1] *= scale2[r];
                    }
            }
            __half2 m20 = __float2half2_rn(mnew2[0]);
            __half2 m21 = __float2half2_rn(mnew2[1]);
            #pragma unroll
            for (int k2 = 0; k2 < 4; k2++) {
                __half2 a0 = __floats2half2_rn(s[fi][2 * k2][0],     s[fi][2 * k2][1]);
                __half2 a1 = __floats2half2_rn(s[fi][2 * k2][2],     s[fi][2 * k2][3]);
                __half2 a2 = __floats2half2_rn(s[fi][2 * k2 + 1][0], s[fi][2 * k2 + 1][1]);
                __half2 a3 = __floats2half2_rn(s[fi][2 * k2 + 1][2], s[fi][2 * k2 + 1][3]);
                __half2 p0 = h2exp2(__hsub2(a0, m20));
                __half2 p1 = h2exp2(__hsub2(a1, m21));
                __half2 p2 = h2exp2(__hsub2(a2, m20));
                __half2 p3 = h2exp2(__hsub2(a3, m21));
                ph2[fi][k2][0] = *(uint32_t*)&p0;
                ph2[fi][k2][1] = *(uint32_t*)&p1;
                ph2[fi][k2][2] = *(uint32_t*)&p2;
                ph2[fi][k2][3] = *(uint32_t*)&p3;
            }
        }

        // O(+l) += P @ [V | 1] — single V pass, fragments double-buffered
        {
            uint32_t vf[2][4];
            ldsm4(vf[0], Vb);   // (k2=0, p=0)
            #pragma unroll
            for (int i = 0; i < 16; i++) {
                int cur = i & 1;
                if (i < 15) {
                    int j = i + 1;
                    ldsm4(vf[cur ^ 1],
                          Vb + (uint32_t)((j & 3) * 2304 + (j >> 2) * 32));
                }
                int k2 = i >> 2, p = i & 3;
                mma16816h(o[0][2 * p],     ph2[0][k2], vf[cur][0], vf[cur][1]);
                mma16816h(o[0][2 * p + 1], ph2[0][k2], vf[cur][2], vf[cur][3]);
                mma16816h(o[1][2 * p],     ph2[1][k2], vf[cur][0], vf[cur][1]);
                mma16816h(o[1][2 * p + 1], ph2[1][k2], vf[cur][2], vf[cur][3]);
                if (p == 3) {
                    mma16816h(o[0][8], ph2[0][k2], ones, ones);
                    mma16816h(o[1][8], ph2[1][k2], ones, ones);
                }
            }
        }
        sidx = (sidx + 1 == 3) ? 0 : sidx + 1;
    }

    // write normalized output (single fp16)
    int src = lane & 28;
    #pragma unroll
    for (int fi = 0; fi < 2; fi++) {
        float l0 = __shfl_sync(0xffffffffu, o[fi][8][0], src);
        float l1 = __shfl_sync(0xffffffffu, o[fi][8][2], src);
        float inv0 = 1.0f / l0;
        float inv1 = 1.0f / l1;
        int r0 = q0 + wm * 32 + fi * 16 + g;
        size_t off0 = ((size_t)bb * S_ + r0) * D_ + hh * HD_;
        size_t off1 = ((size_t)bb * S_ + r0 + 8) * D_ + hh * HD_;
        #pragma unroll
        for (int fj = 0; fj < 8; fj++) {
            int cl = fj * 8 + 2 * t;
            *(uint32_t*)&g_ah[off0 + cl] = pack_h2(o[fi][fj][0] * inv0, o[fi][fj][1] * inv0);
            *(uint32_t*)&g_ah[off1 + cl] = pack_h2(o[fi][fj][2] * inv1, o[fi][fj][3] * inv1);
        }
    }
}

// ---------------------------------------------------------------------------
extern "C" void kernel_launch(void* const* d_in, const int* in_sizes, int n_in,
                              void* d_out, int out_size)
{
    const float* query = (const float*)d_in[0];
    const float* key_  = (const float*)d_in[1];
    const float* value = (const float*)d_in[2];
    // d_in[3] = mask (tril) — handled analytically as causal
    const float* Wq = (const float*)d_in[4];
    const float* bq = (const float*)d_in[5];
    const float* Wk = (const float*)d_in[6];
    const float* bk = (const float*)d_in[7];
    const float* Wv = (const float*)d_in[8];
    const float* bv = (const float*)d_in[9];
    const float* Wo = (const float*)d_in[10];
    const float* bo = (const float*)d_in[11];
    float* out = (float*)d_out;

    cudaFuncSetAttribute(proj_qkv,    cudaFuncAttributeMaxDynamicSharedMemorySize, GEMM_SMEM);
    cudaFuncSetAttribute(proj_out,    cudaFuncAttributeMaxDynamicSharedMemorySize, GEMM_SMEM);
    cudaFuncSetAttribute(attn_kernel, cudaFuncAttributeMaxDynamicSharedMemorySize, ATT_SMEM);

    split_wts<<<dim3(64, 4), 256>>>(Wq, Wk, Wv, Wo);

    dim3 gproj(D_ / 128, MROWS / 128, 3);
    proj_qkv<<<gproj, 256, GEMM_SMEM>>>(query, key_, value, bq, bk, bv);

    dim3 gattn(S_ / 128, B_ * H_);
    attn_kernel<<<gattn, 128, ATT_SMEM>>>();

    dim3 gout(D_ / 128, MROWS / 128);
    proj_out<<<gout, 256, GEMM_SMEM>>>(bo, out);
}

// round 16
// speedup vs baseline: 1.0096x; 1.0096x over previous
#include <cuda_runtime.h>
#include <cuda_bf16.h>
#include <cuda_fp16.h>
#include <stdint.h>

#define B_  2
#define S_  4096
#define D_  768
#define H_  12
#define HD_ 64
#define MROWS 8192
#define NELEM (B_*H_*S_*HD_)

// weights single fp16 (activations converted in-GEMM)
__device__ __half g_wqh[D_*D_], g_wkh[D_*D_], g_wvh[D_*D_], g_woh[D_*D_];
// projected Q/K: [b][h][s][hd] fp16 (Q pre-scaled by 0.125*log2e); V transposed [b][h][hd][s] fp16
__device__ __half g_qh[NELEM], g_kh[NELEM], g_vth[NELEM];
// attention output fp16 [b][s][d]
__device__ __half g_ah[MROWS*D_];

// ---------------------------------------------------------------------------
__device__ __forceinline__ uint32_t pack_h2(float x0, float x1) {
    uint32_t r;
    asm("cvt.rn.f16x2.f32 %0, %1, %2;" : "=r"(r) : "f"(x1), "f"(x0));
    return r;
}
__device__ __forceinline__ void mma16816h(float (&c)[4], const uint32_t (&a)[4],
                                          uint32_t b0, uint32_t b1) {
    asm volatile(
        "mma.sync.aligned.m16n8k16.row.col.f32.f16.f16.f32 "
        "{%0,%1,%2,%3}, {%4,%5,%6,%7}, {%8,%9}, {%0,%1,%2,%3};\n"
        : "+f"(c[0]), "+f"(c[1]), "+f"(c[2]), "+f"(c[3])
        : "r"(a[0]), "r"(a[1]), "r"(a[2]), "r"(a[3]), "r"(b0), "r"(b1));
}
__device__ __forceinline__ void ldsm4(uint32_t (&r)[4], uint32_t addr) {
    asm volatile("ldmatrix.sync.aligned.m8n8.x4.shared.b16 {%0,%1,%2,%3}, [%4];"
        : "=r"(r[0]), "=r"(r[1]), "=r"(r[2]), "=r"(r[3]) : "r"(addr));
}
__device__ __forceinline__ uint32_t smem_u32(const void* p) {
    uint32_t a;
    asm("{ .reg .u64 t; cvta.to.shared.u64 t, %1; cvt.u32.u64 %0, t; }" : "=r"(a) : "l"(p));
    return a;
}
__device__ __forceinline__ void cp16(uint32_t d, const void* s) {
    asm volatile("cp.async.cg.shared.global [%0], [%1], 16;" :: "r"(d), "l"(s));
}
__device__ __forceinline__ void cp_commit() { asm volatile("cp.async.commit_group;"); }
template<int N> __device__ __forceinline__ void cp_wait() {
    asm volatile("cp.async.wait_group %0;" :: "n"(N));
}

// ---------------------------------------------------------------------------
// prep: weights -> single fp16
// ---------------------------------------------------------------------------
__global__ void split_wts(const float* __restrict__ wq, const float* __restrict__ wk,
                          const float* __restrict__ wv, const float* __restrict__ wo) {
    int z = blockIdx.y;
    const float* src = (z == 0) ? wq : (z == 1) ? wk : (z == 2) ? wv : wo;
    __half* h = (z == 0) ? g_wqh : (z == 1) ? g_wkh : (z == 2) ? g_wvh : g_woh;
    int n4 = D_ * D_ / 4;
    for (int i = blockIdx.x * blockDim.x + threadIdx.x; i < n4;
         i += gridDim.x * blockDim.x) {
        float4 v4 = ((const float4*)src)[i];
        uint2 hw;
        hw.x = pack_h2(v4.x, v4.y);
        hw.y = pack_h2(v4.z, v4.w);
        ((uint2*)h)[i] = hw;
    }
}

// ---------------------------------------------------------------------------
// GEMM: C = X @ W^T + bias. W fp16 via cp.async (3-stage ring, one barrier
// per stage). X fp32 (fused cvt) or fp16 (cp.async). 128x128x32 tiles,
// 256 thr = 8 warps (4m x 2n). LDSM B-fragments double-buffered.
// ---------------------------------------------------------------------------
#define GSTG 5120
#define GEMM_SMEM (3 * GSTG * 4)

template<bool XF32>
__device__ __forceinline__ void gemm_core(
    const float* __restrict__ Xf, const __half* __restrict__ Xh,
    const __half* __restrict__ Wh,
    const float* __restrict__ bias, float osc, int emode,
    __half* __restrict__ outh, float* __restrict__ outf)
{
    extern __shared__ uint32_t sm[];
    const uint32_t smb = smem_u32(sm);

    const int tid  = threadIdx.x;
    const int lane = tid & 31;
    const int warp = tid >> 5;
    const int wm = warp >> 1, wn = warp & 1;
    const int g = lane >> 2, t = lane & 3;
    const int m0 = blockIdx.y * 128;
    const int n0 = blockIdx.x * 128;

    const uint32_t la = (uint32_t)(((wm * 32 + (lane & 7) + ((lane >> 3) & 1) * 8) * 20) * 4
                                   + ((lane >> 4) & 1) * 16);
    const uint32_t lb = (uint32_t)(((wn * 64 + ((lane >> 4) & 1) * 8 + (lane & 7)) * 20) * 4
                                   + ((lane >> 3) & 1) * 16);

    auto issueW = [&](int kt, int s) {
        int k0 = kt * 32;
        #pragma unroll
        for (int p = 0; p < 2; p++) {
            int idx = p * 256 + tid;
            int r = idx >> 2, c8 = (idx & 3) * 8;
            uint32_t dst = smb + (uint32_t)((s * GSTG + 2560 + r * 20 + (c8 >> 1)) * 4);
            cp16(dst, Wh + (size_t)(n0 + r) * D_ + k0 + c8);
        }
        cp_commit();
    };
    auto issueXW = [&](int kt, int s) {
        int k0 = kt * 32;
        #pragma unroll
        for (int p = 0; p < 2; p++) {
            int idx = p * 256 + tid;
            int r = idx >> 2, c8 = (idx & 3) * 8;
            uint32_t dst = smb + (uint32_t)((s * GSTG + r * 20 + (c8 >> 1)) * 4);
            cp16(dst,            Xh + (size_t)(m0 + r) * D_ + k0 + c8);
            cp16(dst + 2560 * 4, Wh + (size_t)(n0 + r) * D_ + k0 + c8);
        }
        cp_commit();
    };

    float4 pa[4];
    auto loadX = [&](int kt) {
        int k0 = kt * 32;
        #pragma unroll
        for (int p = 0; p < 2; p++) {
            int idx = p * 256 + tid;
            int r = idx >> 2, c8 = (idx & 3) * 8;
            const float* src = Xf + (size_t)(m0 + r) * D_ + k0 + c8;
            pa[p * 2]     = *(const float4*)src;
            pa[p * 2 + 1] = *(const float4*)(src + 4);
        }
    };
    auto stsX = [&](int s) {
        #pragma unroll
        for (int p = 0; p < 2; p++) {
            int idx = p * 256 + tid;
            int r = idx >> 2, c8 = (idx & 3) * 8;
            uint32_t dst = smb + (uint32_t)((s * GSTG + r * 20 + (c8 >> 1)) * 4);
            uint32_t w0 = pack_h2(pa[p * 2].x,     pa[p * 2].y);
            uint32_t w1 = pack_h2(pa[p * 2].z,     pa[p * 2].w);
            uint32_t w2 = pack_h2(pa[p * 2 + 1].x, pa[p * 2 + 1].y);
            uint32_t w3 = pack_h2(pa[p * 2 + 1].z, pa[p * 2 + 1].w);
            asm volatile("st.shared.v4.b32 [%0], {%1,%2,%3,%4};"
                :: "r"(dst), "r"(w0), "r"(w1), "r"(w2), "r"(w3));
        }
    };

    float c[2][8][4];
    #pragma unroll
    for (int fi = 0; fi < 2; fi++)
        #pragma unroll
        for (int fj = 0; fj < 8; fj++)
            #pragma unroll
            for (int e = 0; e < 4; e++) c[fi][fj][e] = 0.0f;

    if (XF32) {
        loadX(0);
        stsX(0);
        loadX(1);
        issueW(0, 0);
        issueW(1, 1);
    } else {
        issueXW(0, 0);
        issueXW(1, 1);
    }

    int sidx = 0;
    for (int kt = 0; kt < 24; kt++) {
        if (kt < 23) cp_wait<1>();
        else         cp_wait<0>();
        __syncthreads();

        int sn = sidx + 2; if (sn >= 3) sn -= 3;
        if (XF32) {
            if (kt + 1 < 24) {
                int s1 = sidx + 1; if (s1 >= 3) s1 -= 3;
                stsX(s1);
            }
            if (kt + 2 < 24) {
                loadX(kt + 2);
                issueW(kt + 2, sn);
            }
        } else {
            if (kt + 2 < 24) issueXW(kt + 2, sn);
        }

        uint32_t Ab = smb + (uint32_t)(sidx * GSTG * 4);
        uint32_t Bb = Ab + 2560 * 4;

        #pragma unroll
        for (int ks = 0; ks < 2; ks++) {
            uint32_t ah[2][4];
            #pragma unroll
            for (int fi = 0; fi < 2; fi++)
                ldsm4(ah[fi], Ab + la + (uint32_t)(fi * 16 * 20 * 4 + ks * 32));
            uint32_t bf[2][4];
            ldsm4(bf[0], Bb + lb + (uint32_t)(ks * 32));
            #pragma unroll
            for (int p = 0; p < 4; p++) {
                int cur = p & 1;
                if (p < 3)
                    ldsm4(bf[cur ^ 1], Bb + lb + (uint32_t)((p + 1) * 16 * 20 * 4 + ks * 32));
                #pragma unroll
                for (int fi = 0; fi < 2; fi++) {
                    mma16816h(c[fi][2 * p],     ah[fi], bf[cur][0], bf[cur][1]);
                    mma16816h(c[fi][2 * p + 1], ah[fi], bf[cur][2], bf[cur][3]);
                }
            }
        }
        sidx = (sidx + 1 == 3) ? 0 : sidx + 1;
    }

    #pragma unroll
    for (int fi = 0; fi < 2; fi++) {
        #pragma unroll
        for (int rr = 0; rr < 2; rr++) {
            int m = m0 + wm * 32 + fi * 16 + g + rr * 8;
            #pragma unroll
            for (int fj = 0; fj < 8; fj++) {
                int n = n0 + wn * 64 + fj * 8 + 2 * t;
                float v0 = c[fi][fj][rr * 2 + 0] + bias[n];
                float v1 = c[fi][fj][rr * 2 + 1] + bias[n + 1];
                if (emode <= 1) {
                    v0 *= osc; v1 *= osc;
                    int bb = m >> 12, ss = m & 4095;
                    int hh = n >> 6,  hd = n & 63;
                    size_t off = (((size_t)bb * H_ + hh) * S_ + ss) * HD_ + hd;
                    *(uint32_t*)&outh[off] = pack_h2(v0, v1);
                } else if (emode == 2) {
                    int bb = m >> 12, ss = m & 4095;
                    int hh = n >> 6,  hd = n & 63;
                    size_t base = (((size_t)bb * H_ + hh) * HD_ + hd) * S_ + ss;
                    outh[base]      = __float2half_rn(v0);
                    outh[base + S_] = __float2half_rn(v1);
                } else {
                    float2 o2; o2.x = v0; o2.y = v1;
                    *(float2*)&outf[(size_t)m * D_ + n] = o2;
                }
            }
        }
    }
}

__global__ void __launch_bounds__(256, 2) proj_qkv(
    const float* __restrict__ xq, const float* __restrict__ xk, const float* __restrict__ xv,
    const float* __restrict__ bq, const float* __restrict__ bk, const float* __restrict__ bv)
{
    int z = blockIdx.z;
    const float* Xf = (z == 0) ? xq : (z == 1) ? xk : xv;
    const __half* Wh = (z == 0) ? g_wqh : (z == 1) ? g_wkh : g_wvh;
    const float* bias = (z == 0) ? bq : (z == 1) ? bk : bv;
    __half* oh = (z == 0) ? g_qh : (z == 1) ? g_kh : g_vth;
    float osc = (z == 0) ? (0.125f * 1.44269504f) : 1.0f;   // Q: fold 1/8 and log2(e)
    gemm_core<true>(Xf, nullptr, Wh, bias, osc, z, oh, nullptr);
}

__global__ void __launch_bounds__(256, 2) proj_out(
    const float* __restrict__ bo, float* __restrict__ out)
{
    gemm_core<false>(nullptr, g_ah, g_woh, bo, 1.0f, 3, nullptr, out);
}

// ---------------------------------------------------------------------------
// Flash attention, causal, single-fp16 MMA, log2-domain softmax, l via
// constant ones B-fragment. 128 q-rows/CTA (4 warps x 32 rows), 64-key tiles.
// 3-stage cp.async ring, ONE barrier per tile. Fully-masked tiles skipped
// per warp (provable no-op). Softmax phase-split for shfl ILP. PV single
// pass, LDSM double-buffered. Stage: K 64x36, V 64x36 words.
// ---------------------------------------------------------------------------
#define ASTG 4608   // words per stage
#define ATT_SMEM (3 * ASTG * 4)

__global__ void __launch_bounds__(128, 2) attn_kernel()
{
    extern __shared__ uint32_t sm[];
    const uint32_t smb = smem_u32(sm);

    const int tid  = threadIdx.x;
    const int lane = tid & 31;
    const int wm   = tid >> 5;
    const int g    = lane >> 2;
    const int t    = lane & 3;
    const int qt = gridDim.x - 1 - blockIdx.x;   // heavy CTAs first
    const int bh = blockIdx.y;
    const int bb = bh / H_;
    const int hh = bh % H_;
    const int q0 = qt * 128;
    const int ntiles = 2 * qt + 2;

    const uint32_t lk = (uint32_t)(((((lane >> 4) & 1) * 8 + (lane & 7)) * 36) * 4
                                   + ((lane >> 3) & 1) * 16);
    const uint32_t ones = (lane < 4) ? 0x3C003C00u : 0u;

    auto issue = [&](int jt, int s) {
        int k0 = jt * 64;
        #pragma unroll
        for (int p = 0; p < 4; p++) {
            int idx = p * 128 + tid;
            int row = idx >> 3, c8 = (idx & 7) * 8;
            uint32_t dstK = smb + (uint32_t)((s * ASTG + row * 36 + (c8 >> 1)) * 4);
            cp16(dstK,            g_kh  + ((size_t)bh * S_ + k0 + row) * HD_ + c8);
            cp16(dstK + 2304 * 4, g_vth + ((size_t)bh * HD_ + row) * S_ + k0 + c8);
        }
        cp_commit();
    };

    issue(0, 0);
    issue(1, 1);

    uint32_t qh[2][4][4];
    #pragma unroll
    for (int fi = 0; fi < 2; fi++) {
        const __half* qb = g_qh + ((size_t)bh * S_ + q0 + wm * 32 + fi * 16) * HD_;
        #pragma unroll
        for (int kt = 0; kt < 4; kt++) {
            int kc = kt * 16 + 2 * t;
            qh[fi][kt][0] = *(const uint32_t*)&qb[(size_t)g * HD_ + kc];
            qh[fi][kt][1] = *(const uint32_t*)&qb[(size_t)(g + 8) * HD_ + kc];
            qh[fi][kt][2] = *(const uint32_t*)&qb[(size_t)g * HD_ + kc + 8];
            qh[fi][kt][3] = *(const uint32_t*)&qb[(size_t)(g + 8) * HD_ + kc + 8];
        }
    }

    float o[2][9][4];
    float mrun[2][2];
    #pragma unroll
    for (int fi = 0; fi < 2; fi++) {
        mrun[fi][0] = mrun[fi][1] = -1e30f;
        #pragma unroll
        for (int fj = 0; fj < 9; fj++)
            #pragma unroll
            for (int e = 0; e < 4; e++) o[fi][fj][e] = 0.0f;
    }

    const int wrow = q0 + wm * 32;
    int sidx = 0;

    for (int jt = 0; jt < ntiles; jt++) {
        const int k0 = jt * 64;
        if (jt + 1 < ntiles) cp_wait<1>();
        else                 cp_wait<0>();
        __syncthreads();

        if (jt + 2 < ntiles) {
            int sn = sidx + 2; if (sn >= 3) sn -= 3;
            issue(jt + 2, sn);
        }

        // fully-masked tile for this warp: provable no-op (P==0, l+=0, scale==1)
        if (k0 > wrow + 31) {
            sidx = (sidx + 1 == 3) ? 0 : sidx + 1;
            continue;
        }

        uint32_t Kb = smb + (uint32_t)(sidx * ASTG * 4) + lk;
        uint32_t Vb = Kb + 2304 * 4;

        // S = Q @ K^T (log2 units); K fragments double-buffered
        float s[2][8][4];
        #pragma unroll
        for (int fi = 0; fi < 2; fi++)
            #pragma unroll
            for (int fj = 0; fj < 8; fj++)
                #pragma unroll
                for (int e = 0; e < 4; e++) s[fi][fj][e] = 0.0f;

        {
            uint32_t kf[2][4];
            ldsm4(kf[0], Kb);
            #pragma unroll
            for (int i = 0; i < 16; i++) {
                int cur = i & 1;
                if (i < 15) {
                    int j = i + 1;
                    ldsm4(kf[cur ^ 1],
                          Kb + (uint32_t)((j & 3) * 2304 + (j >> 2) * 32));
                }
                int kt = i >> 2, p = i & 3;
                mma16816h(s[0][2 * p],     qh[0][kt], kf[cur][0], kf[cur][1]);
                mma16816h(s[0][2 * p + 1], qh[0][kt], kf[cur][2], kf[cur][3]);
                mma16816h(s[1][2 * p],     qh[1][kt], kf[cur][0], kf[cur][1]);
                mma16816h(s[1][2 * p + 1], qh[1][kt], kf[cur][2], kf[cur][3]);
            }
        }

        if (k0 + 63 > wrow) {
            #pragma unroll
            for (int fi = 0; fi < 2; fi++) {
                int r0 = wrow + fi * 16 + g;
                int r1 = r0 + 8;
                #pragma unroll
                for (int fj = 0; fj < 8; fj++) {
                    int cn = k0 + fj * 8 + 2 * t;
                    if (cn     > r0) s[fi][fj][0] = -1e30f;
                    if (cn + 1 > r0) s[fi][fj][1] = -1e30f;
                    if (cn     > r1) s[fi][fj][2] = -1e30f;
                    if (cn + 1 > r1) s[fi][fj][3] = -1e30f;
                }
            }
        }

        // phase 1: all 4 row-group maxes (independent shfl chains, ILP)
        float mx[2][2];
        #pragma unroll
        for (int fi = 0; fi < 2; fi++)
            #pragma unroll
            for (int r = 0; r < 2; r++) {
                float m = -1e30f;
                #pragma unroll
                for (int fj = 0; fj < 8; fj++)
                    m = fmaxf(m, fmaxf(s[fi][fj][2 * r], s[fi][fj][2 * r + 1]));
                mx[fi][r] = m;
            }
        #pragma unroll
        for (int fi = 0; fi < 2; fi++)
            #pragma unroll
            for (int r = 0; r < 2; r++)
                mx[fi][r] = fmaxf(mx[fi][r], __shfl_xor_sync(0xffffffffu, mx[fi][r], 1));
        #pragma unroll
        for (int fi = 0; fi < 2; fi++)
            #pragma unroll
            for (int r = 0; r < 2; r++)
                mx[fi][r] = fmaxf(mx[fi][r], __shfl_xor_sync(0xffffffffu, mx[fi][r], 2));

        // phase 2: scales + running max update
        float scale2[2][2];
        #pragma unroll
        for (int fi = 0; fi < 2; fi++)
            #pragma unroll
            for (int r = 0; r < 2; r++) {
                float mnew = fmaxf(mrun[fi][r], mx[fi][r]);
                scale2[fi][r] = exp2f(mrun[fi][r] - mnew);
                mrun[fi][r] = mnew;
            }

        // phase 3: combined warp-uniform rescale skip (x1.0 multiplies exact)
        unsigned noscale = __all_sync(0xffffffffu,
            (scale2[0][0] == 1.0f) && (scale2[0][1] == 1.0f) &&
            (scale2[1][0] == 1.0f) && (scale2[1][1] == 1.0f));
        if (!noscale) {
            #pragma unroll
            for (int fi = 0; fi < 2; fi++)
                #pragma unroll
                for (int r = 0; r < 2; r++)
                    #pragma unroll
                    for (int fj = 0; fj < 9; fj++) {
                        o[fi][fj][2 * r]     *= scale2[fi][r];
                        o[fi][fj][2 * r + 1] *= scale2[fi][r];
                    }
        }

        // phase 4: pack P for both halves
        uint32_t ph2[2][4][4];
        #pragma unroll
        for (int fi = 0; fi < 2; fi++) {
            __half2 m20 = __float2half2_rn(mrun[fi][0]);
            __half2 m21 = __float2half2_rn(mrun[fi][1]);
            #pragma unroll
            for (int k2 = 0; k2 < 4; k2++) {
                __half2 a0 = __floats2half2_rn(s[fi][2 * k2][0],     s[fi][2 * k2][1]);
                __half2 a1 = __floats2half2_rn(s[fi][2 * k2][2],     s[fi][2 * k2][3]);
                __half2 a2 = __floats2half2_rn(s[fi][2 * k2 + 1][0], s[fi][2 * k2 + 1][1]);
                __half2 a3 = __floats2half2_rn(s[fi][2 * k2 + 1][2], s[fi][2 * k2 + 1][3]);
                __half2 p0 = h2exp2(__hsub2(a0, m20));
                __half2 p1 = h2exp2(__hsub2(a1, m21));
                __half2 p2 = h2exp2(__hsub2(a2, m20));
                __half2 p3 = h2exp2(__hsub2(a3, m21));
                ph2[fi][k2][0] = *(uint32_t*)&p0;
                ph2[fi][k2][1] = *(uint32_t*)&p1;
                ph2[fi][k2][2] = *(uint32_t*)&p2;
                ph2[fi][k2][3] = *(uint32_t*)&p3;
            }
        }

        // O(+l) += P @ [V | 1] — single V pass, fragments double-buffered
        {
            uint32_t vf[2][4];
            ldsm4(vf[0], Vb);
            #pragma unroll
            for (int i = 0; i < 16; i++) {
                int cur = i & 1;
                if (i < 15) {
                    int j = i + 1;
                    ldsm4(vf[cur ^ 1],
                          Vb + (uint32_t)((j & 3) * 2304 + (j >> 2) * 32));
                }
                int k2 = i >> 2, p = i & 3;
                mma16816h(o[0][2 * p],     ph2[0][k2], vf[cur][0], vf[cur][1]);
                mma16816h(o[0][2 * p + 1], ph2[0][k2], vf[cur][2], vf[cur][3]);
                mma16816h(o[1][2 * p],     ph2[1][k2], vf[cur][0], vf[cur][1]);
                mma16816h(o[1][2 * p + 1], ph2[1][k2], vf[cur][2], vf[cur][3]);
                if (p == 3) {
                    mma16816h(o[0][8], ph2[0][k2], ones, ones);
                    mma16816h(o[1][8], ph2[1][k2], ones, ones);
                }
            }
        }
        sidx = (sidx + 1 == 3) ? 0 : sidx + 1;
    }

    // write normalized output (single fp16)
    int src = lane & 28;
    #pragma unroll
    for (int fi = 0; fi < 2; fi++) {
        float l0 = __shfl_sync(0xffffffffu, o[fi][8][0], src);
        float l1 = __shfl_sync(0xffffffffu, o[fi][8][2], src);
        float inv0 = 1.0f / l0;
        float inv1 = 1.0f / l1;
        int r0 = q0 + wm * 32 + fi * 16 + g;
        size_t off0 = ((size_t)bb * S_ + r0) * D_ + hh * HD_;
        size_t off1 = ((size_t)bb * S_ + r0 + 8) * D_ + hh * HD_;
        #pragma unroll
        for (int fj = 0; fj < 8; fj++) {
            int cl = fj * 8 + 2 * t;
            *(uint32_t*)&g_ah[off0 + cl] = pack_h2(o[fi][fj][0] * inv0, o[fi][fj][1] * inv0);
            *(uint32_t*)&g_ah[off1 + cl] = pack_h2(o[fi][fj][2] * inv1, o[fi][fj][3] * inv1);
        }
    }
}

// ---------------------------------------------------------------------------
extern "C" void kernel_launch(void* const* d_in, const int* in_sizes, int n_in,
                              void* d_out, int out_size)
{
    const float* query = (const float*)d_in[0];
    const float* key_  = (const float*)d_in[1];
    const float* value = (const float*)d_in[2];
    // d_in[3] = mask (tril) — handled analytically as causal
    const float* Wq = (const float*)d_in[4];
    const float* bq = (const float*)d_in[5];
    const float* Wk = (const float*)d_in[6];
    const float* bk = (const float*)d_in[7];
    const float* Wv = (const float*)d_in[8];
    const float* bv = (const float*)d_in[9];
    const float* Wo = (const float*)d_in[10];
    const float* bo = (const float*)d_in[11];
    float* out = (float*)d_out;

    cudaFuncSetAttribute(proj_qkv,    cudaFuncAttributeMaxDynamicSharedMemorySize, GEMM_SMEM);
    cudaFuncSetAttribute(proj_out,    cudaFuncAttributeMaxDynamicSharedMemorySize, GEMM_SMEM);
    cudaFuncSetAttribute(attn_kernel, cudaFuncAttributeMaxDynamicSharedMemorySize, ATT_SMEM);

    split_wts<<<dim3(64, 4), 256>>>(Wq, Wk, Wv, Wo);

    dim3 gproj(D_ / 128, MROWS / 128, 3);
    proj_qkv<<<gproj, 256, GEMM_SMEM>>>(query, key_, value, bq, bk, bv);

    dim3 gattn(S_ / 128, B_ * H_);
    attn_kernel<<<gattn, 128, ATT_SMEM>>>();

    dim3 gout(D_ / 128, MROWS / 128);
    proj_out<<<gout, 256, GEMM_SMEM>>>(bo, out);
}

// round 17
// speedup vs baseline: 1.0291x; 1.0193x over previous
#include <cuda_runtime.h>
#include <cuda_bf16.h>
#include <cuda_fp16.h>
#include <stdint.h>

#define B_  2
#define S_  4096
#define D_  768
#define H_  12
#define HD_ 64
#define MROWS 8192
#define NELEM (B_*H_*S_*HD_)

// weights single fp16 (activations converted in-GEMM)
__device__ __half g_wqh[D_*D_], g_wkh[D_*D_], g_wvh[D_*D_], g_woh[D_*D_];
// projected Q/K: [b][h][s][hd] fp16 (Q pre-scaled by 0.125*log2e); V transposed [b][h][hd][s] fp16
__device__ __half g_qh[NELEM], g_kh[NELEM], g_vth[NELEM];
// attention output fp16 [b][s][d]
__device__ __half g_ah[MROWS*D_];

// ---------------------------------------------------------------------------
__device__ __forceinline__ uint32_t pack_h2(float x0, float x1) {
    uint32_t r;
    asm("cvt.rn.f16x2.f32 %0, %1, %2;" : "=r"(r) : "f"(x1), "f"(x0));
    return r;
}
__device__ __forceinline__ void mma16816h(float (&c)[4], const uint32_t (&a)[4],
                                          uint32_t b0, uint32_t b1) {
    asm volatile(
        "mma.sync.aligned.m16n8k16.row.col.f32.f16.f16.f32 "
        "{%0,%1,%2,%3}, {%4,%5,%6,%7}, {%8,%9}, {%0,%1,%2,%3};\n"
        : "+f"(c[0]), "+f"(c[1]), "+f"(c[2]), "+f"(c[3])
        : "r"(a[0]), "r"(a[1]), "r"(a[2]), "r"(a[3]), "r"(b0), "r"(b1));
}
__device__ __forceinline__ void ldsm4(uint32_t (&r)[4], uint32_t addr) {
    asm volatile("ldmatrix.sync.aligned.m8n8.x4.shared.b16 {%0,%1,%2,%3}, [%4];"
        : "=r"(r[0]), "=r"(r[1]), "=r"(r[2]), "=r"(r[3]) : "r"(addr));
}
__device__ __forceinline__ uint32_t smem_u32(const void* p) {
    uint32_t a;
    asm("{ .reg .u64 t; cvta.to.shared.u64 t, %1; cvt.u32.u64 %0, t; }" : "=r"(a) : "l"(p));
    return a;
}
__device__ __forceinline__ void cp16(uint32_t d, const void* s) {
    asm volatile("cp.async.cg.shared.global [%0], [%1], 16;" :: "r"(d), "l"(s));
}
__device__ __forceinline__ void cp_commit() { asm volatile("cp.async.commit_group;"); }
template<int N> __device__ __forceinline__ void cp_wait() {
    asm volatile("cp.async.wait_group %0;" :: "n"(N));
}

// ---------------------------------------------------------------------------
// prep: weights -> single fp16
// ---------------------------------------------------------------------------
__global__ void split_wts(const float* __restrict__ wq, const float* __restrict__ wk,
                          const float* __restrict__ wv, const float* __restrict__ wo) {
    int z = blockIdx.y;
    const float* src = (z == 0) ? wq : (z == 1) ? wk : (z == 2) ? wv : wo;
    __half* h = (z == 0) ? g_wqh : (z == 1) ? g_wkh : (z == 2) ? g_wvh : g_woh;
    int n4 = D_ * D_ / 4;
    for (int i = blockIdx.x * blockDim.x + threadIdx.x; i < n4;
         i += gridDim.x * blockDim.x) {
        float4 v4 = ((const float4*)src)[i];
        uint2 hw;
        hw.x = pack_h2(v4.x, v4.y);
        hw.y = pack_h2(v4.z, v4.w);
        ((uint2*)h)[i] = hw;
    }
}

// ---------------------------------------------------------------------------
// proj_qkv GEMM: C = X @ W^T + bias; X fp32 (fused cvt), W fp16 cp.async.
// 128x128x32 tiles, 3-stage ring, one barrier per stage. 256 thr = 8 warps.
// ---------------------------------------------------------------------------
#define GSTG 5120
#define GEMM_SMEM (3 * GSTG * 4)

__global__ void __launch_bounds__(256, 2) proj_qkv(
    const float* __restrict__ xq, const float* __restrict__ xk, const float* __restrict__ xv,
    const float* __restrict__ bq, const float* __restrict__ bk, const float* __restrict__ bv)
{
    extern __shared__ uint32_t sm[];
    const uint32_t smb = smem_u32(sm);

    int z = blockIdx.z;
    const float* Xf = (z == 0) ? xq : (z == 1) ? xk : xv;
    const __half* Wh = (z == 0) ? g_wqh : (z == 1) ? g_wkh : g_wvh;
    const float* bias = (z == 0) ? bq : (z == 1) ? bk : bv;
    __half* outh = (z == 0) ? g_qh : (z == 1) ? g_kh : g_vth;
    float osc = (z == 0) ? (0.125f * 1.44269504f) : 1.0f;   // Q: fold 1/8 and log2(e)

    const int tid  = threadIdx.x;
    const int lane = tid & 31;
    const int warp = tid >> 5;
    const int wm = warp >> 1, wn = warp & 1;
    const int g = lane >> 2, t = lane & 3;
    const int m0 = blockIdx.y * 128;
    const int n0 = blockIdx.x * 128;

    const uint32_t la = (uint32_t)(((wm * 32 + (lane & 7) + ((lane >> 3) & 1) * 8) * 20) * 4
                                   + ((lane >> 4) & 1) * 16);
    const uint32_t lb = (uint32_t)(((wn * 64 + ((lane >> 4) & 1) * 8 + (lane & 7)) * 20) * 4
                                   + ((lane >> 3) & 1) * 16);

    auto issueW = [&](int kt, int s) {
        int k0 = kt * 32;
        #pragma unroll
        for (int p = 0; p < 2; p++) {
            int idx = p * 256 + tid;
            int r = idx >> 2, c8 = (idx & 3) * 8;
            uint32_t dst = smb + (uint32_t)((s * GSTG + 2560 + r * 20 + (c8 >> 1)) * 4);
            cp16(dst, Wh + (size_t)(n0 + r) * D_ + k0 + c8);
        }
        cp_commit();
    };

    float4 pa[4];
    auto loadX = [&](int kt) {
        int k0 = kt * 32;
        #pragma unroll
        for (int p = 0; p < 2; p++) {
            int idx = p * 256 + tid;
            int r = idx >> 2, c8 = (idx & 3) * 8;
            const float* src = Xf + (size_t)(m0 + r) * D_ + k0 + c8;
            pa[p * 2]     = *(const float4*)src;
            pa[p * 2 + 1] = *(const float4*)(src + 4);
        }
    };
    auto stsX = [&](int s) {
        #pragma unroll
        for (int p = 0; p < 2; p++) {
            int idx = p * 256 + tid;
            int r = idx >> 2, c8 = (idx & 3) * 8;
            uint32_t dst = smb + (uint32_t)((s * GSTG + r * 20 + (c8 >> 1)) * 4);
            uint32_t w0 = pack_h2(pa[p * 2].x,     pa[p * 2].y);
            uint32_t w1 = pack_h2(pa[p * 2].z,     pa[p * 2].w);
            uint32_t w2 = pack_h2(pa[p * 2 + 1].x, pa[p * 2 + 1].y);
            uint32_t w3 = pack_h2(pa[p * 2 + 1].z, pa[p * 2 + 1].w);
            asm volatile("st.shared.v4.b32 [%0], {%1,%2,%3,%4};"
                :: "r"(dst), "r"(w0), "r"(w1), "r"(w2), "r"(w3));
        }
    };

    float c[2][8][4];
    #pragma unroll
    for (int fi = 0; fi < 2; fi++)
        #pragma unroll
        for (int fj = 0; fj < 8; fj++)
            #pragma unroll
            for (int e = 0; e < 4; e++) c[fi][fj][e] = 0.0f;

    loadX(0);
    stsX(0);
    loadX(1);
    issueW(0, 0);
    issueW(1, 1);

    int sidx = 0;
    for (int kt = 0; kt < 24; kt++) {
        if (kt < 23) cp_wait<1>();
        else         cp_wait<0>();
        __syncthreads();

        int sn = sidx + 2; if (sn >= 3) sn -= 3;
        if (kt + 1 < 24) {
            int s1 = sidx + 1; if (s1 >= 3) s1 -= 3;
            stsX(s1);
        }
        if (kt + 2 < 24) {
            loadX(kt + 2);
            issueW(kt + 2, sn);
        }

        uint32_t Ab = smb + (uint32_t)(sidx * GSTG * 4);
        uint32_t Bb = Ab + 2560 * 4;

        #pragma unroll
        for (int ks = 0; ks < 2; ks++) {
            uint32_t ah[2][4];
            #pragma unroll
            for (int fi = 0; fi < 2; fi++)
                ldsm4(ah[fi], Ab + la + (uint32_t)(fi * 16 * 20 * 4 + ks * 32));
            uint32_t bf[2][4];
            ldsm4(bf[0], Bb + lb + (uint32_t)(ks * 32));
            #pragma unroll
            for (int p = 0; p < 4; p++) {
                int cur = p & 1;
                if (p < 3)
                    ldsm4(bf[cur ^ 1], Bb + lb + (uint32_t)((p + 1) * 16 * 20 * 4 + ks * 32));
                #pragma unroll
                for (int fi = 0; fi < 2; fi++) {
                    mma16816h(c[fi][2 * p],     ah[fi], bf[cur][0], bf[cur][1]);
                    mma16816h(c[fi][2 * p + 1], ah[fi], bf[cur][2], bf[cur][3]);
                }
            }
        }
        sidx = (sidx + 1 == 3) ? 0 : sidx + 1;
    }

    #pragma unroll
    for (int fi = 0; fi < 2; fi++) {
        #pragma unroll
        for (int rr = 0; rr < 2; rr++) {
            int m = m0 + wm * 32 + fi * 16 + g + rr * 8;
            #pragma unroll
            for (int fj = 0; fj < 8; fj++) {
                int n = n0 + wn * 64 + fj * 8 + 2 * t;
                float v0 = (c[fi][fj][rr * 2 + 0] + bias[n])     * osc;
                float v1 = (c[fi][fj][rr * 2 + 1] + bias[n + 1]) * osc;
                int bb = m >> 12, ss = m & 4095;
                int hh = n >> 6,  hd = n & 63;
                if (z <= 1) {
                    size_t off = (((size_t)bb * H_ + hh) * S_ + ss) * HD_ + hd;
                    *(uint32_t*)&outh[off] = pack_h2(v0, v1);
                } else {
                    size_t base = (((size_t)bb * H_ + hh) * HD_ + hd) * S_ + ss;
                    outh[base]      = __float2half_rn(v0);
                    outh[base + S_] = __float2half_rn(v1);
                }
            }
        }
    }
}

// ---------------------------------------------------------------------------
// proj_out GEMM: out = A @ Wo^T + bo; A,W fp16 cp.async. 128x128x64 stages
// (12 stages), 2-stage ring, 36-word padded rows (conflict-free), one barrier
// per stage. Same K-chunk accumulation order as BK=32 -> bit-exact.
// ---------------------------------------------------------------------------
#define G2STG 9216   // words per stage: A 128x36 + B 128x36
#define GOUT_SMEM (2 * G2STG * 4)

__global__ void __launch_bounds__(256, 2) proj_out(
    const float* __restrict__ bo, float* __restrict__ out)
{
    extern __shared__ uint32_t sm[];
    const uint32_t smb = smem_u32(sm);

    const int tid  = threadIdx.x;
    const int lane = tid & 31;
    const int warp = tid >> 5;
    const int wm = warp >> 1, wn = warp & 1;
    const int g = lane >> 2, t = lane & 3;
    const int m0 = blockIdx.y * 128;
    const int n0 = blockIdx.x * 128;

    const uint32_t la = (uint32_t)(((wm * 32 + (lane & 7) + ((lane >> 3) & 1) * 8) * 36) * 4
                                   + ((lane >> 4) & 1) * 16);
    const uint32_t lb = (uint32_t)(((wn * 64 + ((lane >> 4) & 1) * 8 + (lane & 7)) * 36) * 4
                                   + ((lane >> 3) & 1) * 16);

    auto issue = [&](int kt, int s) {
        int k0 = kt * 64;
        #pragma unroll
        for (int p = 0; p < 4; p++) {
            int idx = p * 256 + tid;                 // 0..1023 over A rows x 8 chunks
            int r = idx >> 3, c16 = (idx & 7) * 16;  // byte offset within 128B row
            uint32_t dst = smb + (uint32_t)((s * G2STG + r * 36) * 4) + (uint32_t)c16;
            cp16(dst,                g_ah  + (size_t)(m0 + r) * D_ + k0 + (c16 >> 1));
            cp16(dst + 4608 * 4,     g_woh + (size_t)(n0 + r) * D_ + k0 + (c16 >> 1));
        }
        cp_commit();
    };

    float c[2][8][4];
    #pragma unroll
    for (int fi = 0; fi < 2; fi++)
        #pragma unroll
        for (int fj = 0; fj < 8; fj++)
            #pragma unroll
            for (int e = 0; e < 4; e++) c[fi][fj][e] = 0.0f;

    issue(0, 0);

    for (int kt = 0; kt < 12; kt++) {
        if (kt < 11) { issue(kt + 1, (kt + 1) & 1); cp_wait<1>(); }
        else         { cp_wait<0>(); }
        __syncthreads();

        uint32_t Ab = smb + (uint32_t)((kt & 1) * G2STG * 4);
        uint32_t Bb = Ab + 4608 * 4;

        #pragma unroll
        for (int ks = 0; ks < 4; ks++) {
            uint32_t ah[2][4];
            #pragma unroll
            for (int fi = 0; fi < 2; fi++)
                ldsm4(ah[fi], Ab + la + (uint32_t)(fi * 16 * 36 * 4 + ks * 32));
            uint32_t bf[2][4];
            ldsm4(bf[0], Bb + lb + (uint32_t)(ks * 32));
            #pragma unroll
            for (int p = 0; p < 4; p++) {
                int cur = p & 1;
                if (p < 3)
                    ldsm4(bf[cur ^ 1], Bb + lb + (uint32_t)((p + 1) * 16 * 36 * 4 + ks * 32));
                #pragma unroll
                for (int fi = 0; fi < 2; fi++) {
                    mma16816h(c[fi][2 * p],     ah[fi], bf[cur][0], bf[cur][1]);
                    mma16816h(c[fi][2 * p + 1], ah[fi], bf[cur][2], bf[cur][3]);
                }
            }
        }
        __syncthreads();
    }

    #pragma unroll
    for (int fi = 0; fi < 2; fi++) {
        #pragma unroll
        for (int rr = 0; rr < 2; rr++) {
            int m = m0 + wm * 32 + fi * 16 + g + rr * 8;
            #pragma unroll
            for (int fj = 0; fj < 8; fj++) {
                int n = n0 + wn * 64 + fj * 8 + 2 * t;
                float2 o2;
                o2.x = c[fi][fj][rr * 2 + 0] + bo[n];
                o2.y = c[fi][fj][rr * 2 + 1] + bo[n + 1];
                *(float2*)&out[(size_t)m * D_ + n] = o2;
            }
        }
    }
}

// ---------------------------------------------------------------------------
// Flash attention, causal, single-fp16 MMA, log2-domain softmax, l via
// constant ones B-fragment. 128 q-rows/CTA (4 warps x 32 rows), 64-key tiles.
// 3-stage cp.async ring, ONE barrier per tile. Fully-masked tiles skipped
// per warp. Phase-split maxes; per-fi warp-uniform rescale skip. PV single
// pass, LDSM double-buffered. Stage: K 64x36, V 64x36 words.
// ---------------------------------------------------------------------------
#define ASTG 4608   // words per stage
#define ATT_SMEM (3 * ASTG * 4)

__global__ void __launch_bounds__(128, 2) attn_kernel()
{
    extern __shared__ uint32_t sm[];
    const uint32_t smb = smem_u32(sm);

    const int tid  = threadIdx.x;
    const int lane = tid & 31;
    const int wm   = tid >> 5;
    const int g    = lane >> 2;
    const int t    = lane & 3;
    const int qt = gridDim.x - 1 - blockIdx.x;   // heavy CTAs first
    const int bh = blockIdx.y;
    const int bb = bh / H_;
    const int hh = bh % H_;
    const int q0 = qt * 128;
    const int ntiles = 2 * qt + 2;

    const uint32_t lk = (uint32_t)(((((lane >> 4) & 1) * 8 + (lane & 7)) * 36) * 4
                                   + ((lane >> 3) & 1) * 16);
    const uint32_t ones = (lane < 4) ? 0x3C003C00u : 0u;

    auto issue = [&](int jt, int s) {
        int k0 = jt * 64;
        #pragma unroll
        for (int p = 0; p < 4; p++) {
            int idx = p * 128 + tid;
            int row = idx >> 3, c8 = (idx & 7) * 8;
            uint32_t dstK = smb + (uint32_t)((s * ASTG + row * 36 + (c8 >> 1)) * 4);
            cp16(dstK,            g_kh  + ((size_t)bh * S_ + k0 + row) * HD_ + c8);
            cp16(dstK + 2304 * 4, g_vth + ((size_t)bh * HD_ + row) * S_ + k0 + c8);
        }
        cp_commit();
    };

    issue(0, 0);
    issue(1, 1);

    uint32_t qh[2][4][4];
    #pragma unroll
    for (int fi = 0; fi < 2; fi++) {
        const __half* qb = g_qh + ((size_t)bh * S_ + q0 + wm * 32 + fi * 16) * HD_;
        #pragma unroll
        for (int kt = 0; kt < 4; kt++) {
            int kc = kt * 16 + 2 * t;
            qh[fi][kt][0] = *(const uint32_t*)&qb[(size_t)g * HD_ + kc];
            qh[fi][kt][1] = *(const uint32_t*)&qb[(size_t)(g + 8) * HD_ + kc];
            qh[fi][kt][2] = *(const uint32_t*)&qb[(size_t)g * HD_ + kc + 8];
            qh[fi][kt][3] = *(const uint32_t*)&qb[(size_t)(g + 8) * HD_ + kc + 8];
        }
    }

    float o[2][9][4];
    float mrun[2][2];
    #pragma unroll
    for (int fi = 0; fi < 2; fi++) {
        mrun[fi][0] = mrun[fi][1] = -1e30f;
        #pragma unroll
        for (int fj = 0; fj < 9; fj++)
            #pragma unroll
            for (int e = 0; e < 4; e++) o[fi][fj][e] = 0.0f;
    }

    const int wrow = q0 + wm * 32;
    int sidx = 0;

    for (int jt = 0; jt < ntiles; jt++) {
        const int k0 = jt * 64;
        if (jt + 1 < ntiles) cp_wait<1>();
        else                 cp_wait<0>();
        __syncthreads();

        if (jt + 2 < ntiles) {
            int sn = sidx + 2; if (sn >= 3) sn -= 3;
            issue(jt + 2, sn);
        }

        // fully-masked tile for this warp: provable no-op
        if (k0 > wrow + 31) {
            sidx = (sidx + 1 == 3) ? 0 : sidx + 1;
            continue;
        }

        uint32_t Kb = smb + (uint32_t)(sidx * ASTG * 4) + lk;
        uint32_t Vb = Kb + 2304 * 4;

        // S = Q @ K^T (log2 units); K fragments double-buffered
        float s[2][8][4];
        #pragma unroll
        for (int fi = 0; fi < 2; fi++)
            #pragma unroll
            for (int fj = 0; fj < 8; fj++)
                #pragma unroll
                for (int e = 0; e < 4; e++) s[fi][fj][e] = 0.0f;

        {
            uint32_t kf[2][4];
            ldsm4(kf[0], Kb);
            #pragma unroll
            for (int i = 0; i < 16; i++) {
                int cur = i & 1;
                if (i < 15) {
                    int j = i + 1;
                    ldsm4(kf[cur ^ 1],
                          Kb + (uint32_t)((j & 3) * 2304 + (j >> 2) * 32));
                }
                int kt = i >> 2, p = i & 3;
                mma16816h(s[0][2 * p],     qh[0][kt], kf[cur][0], kf[cur][1]);
                mma16816h(s[0][2 * p + 1], qh[0][kt], kf[cur][2], kf[cur][3]);
                mma16816h(s[1][2 * p],     qh[1][kt], kf[cur][0], kf[cur][1]);
                mma16816h(s[1][2 * p + 1], qh[1][kt], kf[cur][2], kf[cur][3]);
            }
        }

        if (k0 + 63 > wrow) {
            #pragma unroll
            for (int fi = 0; fi < 2; fi++) {
                int r0 = wrow + fi * 16 + g;
                int r1 = r0 + 8;
                #pragma unroll
                for (int fj = 0; fj < 8; fj++) {
                    int cn = k0 + fj * 8 + 2 * t;
                    if (cn     > r0) s[fi][fj][0] = -1e30f;
                    if (cn + 1 > r0) s[fi][fj][1] = -1e30f;
                    if (cn     > r1) s[fi][fj][2] = -1e30f;
                    if (cn + 1 > r1) s[fi][fj][3] = -1e30f;
                }
            }
        }

        // phase 1: all 4 row-group maxes (independent shfl chains, ILP)
        float mx[2][2];
        #pragma unroll
        for (int fi = 0; fi < 2; fi++)
            #pragma unroll
            for (int r = 0; r < 2; r++) {
                float m = -1e30f;
                #pragma unroll
                for (int fj = 0; fj < 8; fj++)
                    m = fmaxf(m, fmaxf(s[fi][fj][2 * r], s[fi][fj][2 * r + 1]));
                mx[fi][r] = m;
            }
        #pragma unroll
        for (int fi = 0; fi < 2; fi++)
            #pragma unroll
            for (int r = 0; r < 2; r++)
                mx[fi][r] = fmaxf(mx[fi][r], __shfl_xor_sync(0xffffffffu, mx[fi][r], 1));
        #pragma unroll
        for (int fi = 0; fi < 2; fi++)
            #pragma unroll
            for (int r = 0; r < 2; r++)
                mx[fi][r] = fmaxf(mx[fi][r], __shfl_xor_sync(0xffffffffu, mx[fi][r], 2));

        // phase 2: scales + running max; per-fi warp-uniform rescale skip
        float scale2[2][2];
        #pragma unroll
        for (int fi = 0; fi < 2; fi++) {
            #pragma unroll
            for (int r = 0; r < 2; r++) {
                float mnew = fmaxf(mrun[fi][r], mx[fi][r]);
                scale2[fi][r] = exp2f(mrun[fi][r] - mnew);
                mrun[fi][r] = mnew;
            }
            unsigned noscale = __all_sync(0xffffffffu,
                (scale2[fi][0] == 1.0f) && (scale2[fi][1] == 1.0f));
            if (!noscale) {
                #pragma unroll
                for (int r = 0; r < 2; r++)
                    #pragma unroll
                    for (int fj = 0; fj < 9; fj++) {
                        o[fi][fj][2 * r]     *= scale2[fi][r];
                        o[fi][fj][2 * r + 1] *= scale2[fi][r];
                    }
            }
        }

        // phase 3: pack P for both halves
        uint32_t ph2[2][4][4];
        #pragma unroll
        for (int fi = 0; fi < 2; fi++) {
            __half2 m20 = __float2half2_rn(mrun[fi][0]);
            __half2 m21 = __float2half2_rn(mrun[fi][1]);
            #pragma unroll
            for (int k2 = 0; k2 < 4; k2++) {
                __half2 a0 = __floats2half2_rn(s[fi][2 * k2][0],     s[fi][2 * k2][1]);
                __half2 a1 = __floats2half2_rn(s[fi][2 * k2][2],     s[fi][2 * k2][3]);
                __half2 a2 = __floats2half2_rn(s[fi][2 * k2 + 1][0], s[fi][2 * k2 + 1][1]);
                __half2 a3 = __floats2half2_rn(s[fi][2 * k2 + 1][2], s[fi][2 * k2 + 1][3]);
                __half2 p0 = h2exp2(__hsub2(a0, m20));
                __half2 p1 = h2exp2(__hsub2(a1, m21));
                __half2 p2 = h2exp2(__hsub2(a2, m20));
                __half2 p3 = h2exp2(__hsub2(a3, m21));
                ph2[fi][k2][0] = *(uint32_t*)&p0;
                ph2[fi][k2][1] = *(uint32_t*)&p1;
                ph2[fi][k2][2] = *(uint32_t*)&p2;
                ph2[fi][k2][3] = *(uint32_t*)&p3;
            }
        }

        // O(+l) += P @ [V | 1] — single V pass, fragments double-buffered
        {
            uint32_t vf[2][4];
            ldsm4(vf[0], Vb);
            #pragma unroll
            for (int i = 0; i < 16; i++) {
                int cur = i & 1;
                if (i < 15) {
                    int j = i + 1;
                    ldsm4(vf[cur ^ 1],
                          Vb + (uint32_t)((j & 3) * 2304 + (j >> 2) * 32));
                }
                int k2 = i >> 2, p = i & 3;
                mma16816h(o[0][2 * p],     ph2[0][k2], vf[cur][0], vf[cur][1]);
                mma16816h(o[0][2 * p + 1], ph2[0][k2], vf[cur][2], vf[cur][3]);
                mma16816h(o[1][2 * p],     ph2[1][k2], vf[cur][0], vf[cur][1]);
                mma16816h(o[1][2 * p + 1], ph2[1][k2], vf[cur][2], vf[cur][3]);
                if (p == 3) {
                    mma16816h(o[0][8], ph2[0][k2], ones, ones);
                    mma16816h(o[1][8], ph2[1][k2], ones, ones);
                }
            }
        }
        sidx = (sidx + 1 == 3) ? 0 : sidx + 1;
    }

    // write normalized output (single fp16)
    int src = lane & 28;
    #pragma unroll
    for (int fi = 0; fi < 2; fi++) {
        float l0 = __shfl_sync(0xffffffffu, o[fi][8][0], src);
        float l1 = __shfl_sync(0xffffffffu, o[fi][8][2], src);
        float inv0 = 1.0f / l0;
        float inv1 = 1.0f / l1;
        int r0 = q0 + wm * 32 + fi * 16 + g;
        size_t off0 = ((size_t)bb * S_ + r0) * D_ + hh * HD_;
        size_t off1 = ((size_t)bb * S_ + r0 + 8) * D_ + hh * HD_;
        #pragma unroll
        for (int fj = 0; fj < 8; fj++) {
            int cl = fj * 8 + 2 * t;
            *(uint32_t*)&g_ah[off0 + cl] = pack_h2(o[fi][fj][0] * inv0, o[fi][fj][1] * inv0);
            *(uint32_t*)&g_ah[off1 + cl] = pack_h2(o[fi][fj][2] * inv1, o[fi][fj][3] * inv1);
        }
    }
}

// ---------------------------------------------------------------------------
extern "C" void kernel_launch(void* const* d_in, const int* in_sizes, int n_in,
                              void* d_out, int out_size)
{
    const float* query = (const float*)d_in[0];
    const float* key_  = (const float*)d_in[1];
    const float* value = (const float*)d_in[2];
    // d_in[3] = mask (tril) — handled analytically as causal
    const float* Wq = (const float*)d_in[4];
    const float* bq = (const float*)d_in[5];
    const float* Wk = (const float*)d_in[6];
    const float* bk = (const float*)d_in[7];
    const float* Wv = (const float*)d_in[8];
    const float* bv = (const float*)d_in[9];
    const float* Wo = (const float*)d_in[10];
    const float* bo = (const float*)d_in[11];
    float* out = (float*)d_out;

    cudaFuncSetAttribute(proj_qkv,    cudaFuncAttributeMaxDynamicSharedMemorySize, GEMM_SMEM);
    cudaFuncSetAttribute(proj_out,    cudaFuncAttributeMaxDynamicSharedMemorySize, GOUT_SMEM);
    cudaFuncSetAttribute(attn_kernel, cudaFuncAttributeMaxDynamicSharedMemorySize, ATT_SMEM);

    split_wts<<<dim3(64, 4), 256>>>(Wq, Wk, Wv, Wo);

    dim3 gproj(D_ / 128, MROWS / 128, 3);
    proj_qkv<<<gproj, 256, GEMM_SMEM>>>(query, key_, value, bq, bk, bv);

    dim3 gattn(S_ / 128, B_ * H_);
    attn_kernel<<<gattn, 128, ATT_SMEM>>>();

    dim3 gout(D_ / 128, MROWS / 128);
    proj_out<<<gout, 256, GOUT_SMEM>>>(bo, out);
}